// round 17
// baseline (speedup 1.0000x reference)
#include <cuda_runtime.h>
#include <cuda_bf16.h>
#include <cstdint>

#define B 8
#define S 1024
#define DIM 768
#define H 8
#define NEGV -1e10f
#define RS96 0.1020620726159658f  // 1/sqrt(96)
#define NI (B * S)                // 8192 total rows
#define DH 96                     // head dim

// ---------------------------------------------------------------------------
// Scratch (static device globals — allocation-free per harness rules)
// ---------------------------------------------------------------------------
__device__ float g_logit[NI];
__device__ float g_aw[NI];
__device__ float g_R[NI * H];
__device__ float g_T[B * H * DIM];
// bf16 hi/lo splits of inputs
__device__ __nv_bfloat16 g_Xhi[NI * DIM];
__device__ __nv_bfloat16 g_Xlo[NI * DIM];
__device__ __nv_bfloat16 g_Wqhi[DIM * DIM];
__device__ __nv_bfloat16 g_Wqlo[DIM * DIM];
__device__ __nv_bfloat16 g_Wkhi[DIM * DIM];
__device__ __nv_bfloat16 g_Wklo[DIM * DIM];
// head-packed projections: [h][i][d] bf16 hi/lo (RS96 folded into Q)
__device__ __nv_bfloat16 g_Qphi[H * NI * DH];
__device__ __nv_bfloat16 g_Qplo[H * NI * DH];
__device__ __nv_bfloat16 g_Kphi[H * NI * DH];
__device__ __nv_bfloat16 g_Kplo[H * NI * DH];

// ---------------------------------------------------------------------------
#define MMA16816(d, a0, a1, a2, a3, b0, b1)                                    \
    asm volatile("mma.sync.aligned.m16n8k16.row.col.f32.bf16.bf16.f32 "        \
                 "{%0,%1,%2,%3}, {%4,%5,%6,%7}, {%8,%9}, {%0,%1,%2,%3};"       \
                 : "+f"((d)[0]), "+f"((d)[1]), "+f"((d)[2]), "+f"((d)[3])      \
                 : "r"(a0), "r"(a1), "r"(a2), "r"(a3), "r"(b0), "r"(b1))

#define LDSM4(r0, r1, r2, r3, addr)                                            \
    asm volatile("ldmatrix.sync.aligned.m8n8.x4.shared.b16 {%0,%1,%2,%3}, [%4];" \
                 : "=r"(r0), "=r"(r1), "=r"(r2), "=r"(r3) : "r"(addr))

__device__ __forceinline__ uint32_t packbf2(__nv_bfloat16 a, __nv_bfloat16 b) {
    __nv_bfloat162 p(a, b);
    return *reinterpret_cast<uint32_t*>(&p);
}
__device__ __forceinline__ uint32_t smem_u32(const void* p) {
    uint32_t a;
    asm("{ .reg .u64 t; cvta.to.shared.u64 t, %1; cvt.u32.u64 %0, t; }"
        : "=r"(a) : "l"(p));
    return a;
}
__device__ __forceinline__ void cp16(uint32_t dst, const void* src) {
    asm volatile("cp.async.cg.shared.global [%0], [%1], 16;" :: "r"(dst), "l"(src));
}
#define CP_COMMIT() asm volatile("cp.async.commit_group;" ::: "memory")
#define CP_WAIT1() asm volatile("cp.async.wait_group 1;" ::: "memory")
#define CP_WAIT0() asm volatile("cp.async.wait_group 0;" ::: "memory")

// ---------------------------------------------------------------------------
__global__ void k0_zeroR() {
    int i = blockIdx.x * blockDim.x + threadIdx.x;
    if (i < NI * H) g_R[i] = 0.f;
}

// ---------------------------------------------------------------------------
// Ksplit: fp32 -> bf16 hi + bf16 lo. Destinations selected in device code
// (device symbols must never be host-side kernel args).
// ---------------------------------------------------------------------------
__global__ void ksplit_sel(const float* __restrict__ src, int which, int n4) {
    __nv_bfloat16 *hi, *lo;
    if (which == 0)      { hi = g_Xhi;  lo = g_Xlo;  }
    else if (which == 1) { hi = g_Wqhi; lo = g_Wqlo; }
    else                 { hi = g_Wkhi; lo = g_Wklo; }
    int i = blockIdx.x * blockDim.x + threadIdx.x;
    if (i >= n4) return;
    float4 v = ((const float4*)src)[i];
    __nv_bfloat16 h0 = __float2bfloat16(v.x), h1 = __float2bfloat16(v.y);
    __nv_bfloat16 h2 = __float2bfloat16(v.z), h3 = __float2bfloat16(v.w);
    __nv_bfloat16 l0 = __float2bfloat16(v.x - __bfloat162float(h0));
    __nv_bfloat16 l1 = __float2bfloat16(v.y - __bfloat162float(h1));
    __nv_bfloat16 l2 = __float2bfloat16(v.z - __bfloat162float(h2));
    __nv_bfloat16 l3 = __float2bfloat16(v.w - __bfloat162float(h3));
    ((__nv_bfloat162*)hi)[2 * i] = __nv_bfloat162(h0, h1);
    ((__nv_bfloat162*)hi)[2 * i + 1] = __nv_bfloat162(h2, h3);
    ((__nv_bfloat162*)lo)[2 * i] = __nv_bfloat162(l0, l1);
    ((__nv_bfloat162*)lo)[2 * i + 1] = __nv_bfloat162(l2, l3);
}

// ---------------------------------------------------------------------------
// K1a: span logits  l[i] = X[i,:] . w  (masked with NEG where tag==0)
// ---------------------------------------------------------------------------
__global__ void k1a_logits(const float* __restrict__ X,
                           const int* __restrict__ tags,
                           const float* __restrict__ w) {
    int warp = threadIdx.x >> 5, lane = threadIdx.x & 31;
    int row = blockIdx.x * 8 + warp;
    const float4* xr = (const float4*)(X + (size_t)row * DIM);
    const float4* wr = (const float4*)w;
    float s = 0.f;
#pragma unroll
    for (int i = 0; i < 6; i++) {
        float4 a = xr[lane + 32 * i];
        float4 b = wr[lane + 32 * i];
        s += a.x * b.x + a.y * b.y + a.z * b.z + a.w * b.w;
    }
#pragma unroll
    for (int o = 16; o; o >>= 1) s += __shfl_xor_sync(0xffffffffu, s, o);
    if (lane == 0) g_logit[row] = (tags[row] == 0) ? NEGV : s;
}

// ---------------------------------------------------------------------------
__global__ void k1b_softmax() {
    __shared__ float red[256];
    int b = blockIdx.x, t = threadIdx.x;
    float l[4];
#pragma unroll
    for (int i = 0; i < 4; i++) l[i] = g_logit[b * S + t + 256 * i];
    float mx = fmaxf(fmaxf(l[0], l[1]), fmaxf(l[2], l[3]));
    red[t] = mx;
    __syncthreads();
    for (int o = 128; o; o >>= 1) {
        if (t < o) red[t] = fmaxf(red[t], red[t + o]);
        __syncthreads();
    }
    mx = red[0];
    __syncthreads();
    float e[4], sum = 0.f;
#pragma unroll
    for (int i = 0; i < 4; i++) { e[i] = __expf(l[i] - mx); sum += e[i]; }
    red[t] = sum;
    __syncthreads();
    for (int o = 128; o; o >>= 1) {
        if (t < o) red[t] += red[t + o];
        __syncthreads();
    }
    float inv = 1.f / red[0];
#pragma unroll
    for (int i = 0; i < 4; i++) g_aw[b * S + t + 256 * i] = e[i] * inv;
}

// ---------------------------------------------------------------------------
// K2 (mma.sync bf16x3, VERIFIED math) + cp.async double-buffer pipeline.
// 72 flattened stages (3 terms x 24 k-chunks). Dynamic smem: 2 x 20480 B
// buffers; Cs epilogue overlays buffer 0.
// ---------------------------------------------------------------------------
#define K2_BUF 10240  // elems per buffer: As 128*40 + Bq 64*40 + Bk 64*40
__global__ void __launch_bounds__(256, 2) k2_mma() {
    extern __shared__ __align__(16) __nv_bfloat16 sm2[];
    float* Cs = (float*)sm2;  // [128][66] overlay (after mainloop)
    int t = threadIdx.x, l = t & 31, wid = t >> 5;
    int wm = wid & 3, wn = wid >> 2;
    int i0 = blockIdx.x * 128, j0 = blockIdx.y * 64;
    int lg = l >> 2;         // groupID 0..7
    int lk2 = 2 * (l & 3);   // k-pair base 0,2,4,6
    uint32_t sb = smem_u32(sm2);
    int ar = t >> 2, ac = (t & 3) * 8;

    float qacc[2][4][4], kacc[2][4][4];
#pragma unroll
    for (int am = 0; am < 2; am++)
#pragma unroll
        for (int bn = 0; bn < 4; bn++)
#pragma unroll
            for (int r = 0; r < 4; r++) { qacc[am][bn][r] = 0.f; kacc[am][bn][r] = 0.f; }

    // stage s: term = s/24 (0:hi*hi 1:lo*hi 2:hi*lo), kb = (s%24)*32
    auto issue = [&](int s) {
        const __nv_bfloat16* XA = (s >= 24 && s < 48) ? g_Xlo : g_Xhi;
        const __nv_bfloat16* WQ = (s < 48) ? g_Wqhi : g_Wqlo;
        const __nv_bfloat16* WK = (s < 48) ? g_Wkhi : g_Wklo;
        int kb = (s % 24) * 32;
        uint32_t base = sb + (uint32_t)(s & 1) * (K2_BUF * 2);
        cp16(base + (ar * 40 + ac) * 2, XA + (size_t)(i0 + ar) * DIM + kb + ac);
        cp16(base + ((ar + 64) * 40 + ac) * 2, XA + (size_t)(i0 + ar + 64) * DIM + kb + ac);
        cp16(base + (5120 + ar * 40 + ac) * 2, WQ + (size_t)(j0 + ar) * DIM + kb + ac);
        cp16(base + (7680 + ar * 40 + ac) * 2, WK + (size_t)(j0 + ar) * DIM + kb + ac);
    };

    issue(0);
    CP_COMMIT();
    for (int s = 0; s < 72; s++) {
        if (s < 71) { issue(s + 1); CP_COMMIT(); CP_WAIT1(); }
        else CP_WAIT0();
        __syncthreads();
        const __nv_bfloat16* As = sm2 + (s & 1) * K2_BUF;
        const __nv_bfloat16* Bq = As + 5120;
        const __nv_bfloat16* Bk = As + 7680;
#pragma unroll
        for (int kk = 0; kk < 2; kk++) {
            int ko = kk * 16;
            uint32_t a[2][4];
#pragma unroll
            for (int am = 0; am < 2; am++) {
                const __nv_bfloat16* ap = As + (wm * 32 + am * 16 + lg) * 40 + ko + lk2;
                a[am][0] = *(const uint32_t*)(ap);
                a[am][1] = *(const uint32_t*)(ap + 8 * 40);
                a[am][2] = *(const uint32_t*)(ap + 8);
                a[am][3] = *(const uint32_t*)(ap + 8 * 40 + 8);
            }
#pragma unroll
            for (int bp = 0; bp < 2; bp++)
#pragma unroll
                for (int o = 0; o < 2; o++) {
                    int nr = wn * 32 + bp * 16 + o * 8 + lg;
                    const __nv_bfloat16* bqp = Bq + nr * 40 + ko + lk2;
                    uint32_t q0 = *(const uint32_t*)(bqp);
                    uint32_t q1 = *(const uint32_t*)(bqp + 8);
                    MMA16816(qacc[0][2 * bp + o], a[0][0], a[0][1], a[0][2], a[0][3], q0, q1);
                    MMA16816(qacc[1][2 * bp + o], a[1][0], a[1][1], a[1][2], a[1][3], q0, q1);
                    const __nv_bfloat16* bkp = Bk + nr * 40 + ko + lk2;
                    uint32_t k0 = *(const uint32_t*)(bkp);
                    uint32_t k1 = *(const uint32_t*)(bkp + 8);
                    MMA16816(kacc[0][2 * bp + o], a[0][0], a[0][1], a[0][2], a[0][3], k0, k1);
                    MMA16816(kacc[1][2 * bp + o], a[1][0], a[1][1], a[1][2], a[1][3], k0, k1);
                }
        }
        __syncthreads();
    }

    int d0 = j0 >> 3;
    // ---- Q pass (RS96 folded) ----
#pragma unroll
    for (int am = 0; am < 2; am++)
#pragma unroll
        for (int bn = 0; bn < 4; bn++) {
            int r0 = wm * 32 + am * 16 + lg;
            int c = wn * 32 + bn * 8 + lk2;
            Cs[r0 * 66 + c] = qacc[am][bn][0];
            Cs[r0 * 66 + c + 1] = qacc[am][bn][1];
            Cs[(r0 + 8) * 66 + c] = qacc[am][bn][2];
            Cs[(r0 + 8) * 66 + c + 1] = qacc[am][bn][3];
        }
    __syncthreads();
#pragma unroll
    for (int u = 0; u < 4; u++) {
        int rowid = t + 256 * u;
        int h = rowid & 7, i = rowid >> 3;
        uint4 hv, lv;
        uint32_t* hp = (uint32_t*)&hv;
        uint32_t* lp = (uint32_t*)&lv;
#pragma unroll
        for (int dd = 0; dd < 4; dd++) {
            float v0 = Cs[i * 66 + h + 8 * (2 * dd)] * RS96;
            float v1 = Cs[i * 66 + h + 8 * (2 * dd + 1)] * RS96;
            __nv_bfloat16 h0 = __float2bfloat16(v0), h1 = __float2bfloat16(v1);
            __nv_bfloat16 l0 = __float2bfloat16(v0 - __bfloat162float(h0));
            __nv_bfloat16 l1 = __float2bfloat16(v1 - __bfloat162float(h1));
            hp[dd] = packbf2(h0, h1);
            lp[dd] = packbf2(l0, l1);
        }
        size_t off = ((size_t)h * NI + i0 + i) * DH + d0;
        *(uint4*)(g_Qphi + off) = hv;
        *(uint4*)(g_Qplo + off) = lv;
    }
    // ---- K pass ----
    __syncthreads();
#pragma unroll
    for (int am = 0; am < 2; am++)
#pragma unroll
        for (int bn = 0; bn < 4; bn++) {
            int r0 = wm * 32 + am * 16 + lg;
            int c = wn * 32 + bn * 8 + lk2;
            Cs[r0 * 66 + c] = kacc[am][bn][0];
            Cs[r0 * 66 + c + 1] = kacc[am][bn][1];
            Cs[(r0 + 8) * 66 + c] = kacc[am][bn][2];
            Cs[(r0 + 8) * 66 + c + 1] = kacc[am][bn][3];
        }
    __syncthreads();
#pragma unroll
    for (int u = 0; u < 4; u++) {
        int rowid = t + 256 * u;
        int h = rowid & 7, i = rowid >> 3;
        uint4 hv, lv;
        uint32_t* hp = (uint32_t*)&hv;
        uint32_t* lp = (uint32_t*)&lv;
#pragma unroll
        for (int dd = 0; dd < 4; dd++) {
            float v0 = Cs[i * 66 + h + 8 * (2 * dd)];
            float v1 = Cs[i * 66 + h + 8 * (2 * dd + 1)];
            __nv_bfloat16 h0 = __float2bfloat16(v0), h1 = __float2bfloat16(v1);
            __nv_bfloat16 l0 = __float2bfloat16(v0 - __bfloat162float(h0));
            __nv_bfloat16 l1 = __float2bfloat16(v1 - __bfloat162float(h1));
            hp[dd] = packbf2(h0, h1);
            lp[dd] = packbf2(l0, l1);
        }
        size_t off = ((size_t)h * NI + i0 + i) * DH + d0;
        *(uint4*)(g_Kphi + off) = hv;
        *(uint4*)(g_Kplo + off) = lv;
    }
}

// ---------------------------------------------------------------------------
// K3 (mma.sync bf16x3, VERIFIED per-warp math) — 256-thread CTAs, q64 x k32
// tiles, single-buffered 73.7 KB smem -> 2 CTAs/SM (cross-CTA overlap hides
// loads, syncs, and the epilogue). ldmatrix.x4 fragments, 6 d16 stages.
// ---------------------------------------------------------------------------
#define K3_QT (8 * 64 * 24)  // 12288 elems
#define K3_KT (8 * 32 * 24)  //  6144 elems
#define K3_BUFB ((K3_QT * 2 + K3_KT * 2) * 2)  // bytes: 73728
__global__ void __launch_bounds__(256, 2) k3_attn() {
    extern __shared__ __align__(16) __nv_bfloat16 sm3[];
    __shared__ float Rs[32][8];
    int b = blockIdx.z, q0 = blockIdx.y * 64, k0 = blockIdx.x * 32;
    int t = threadIdx.x, l = t & 31, wid = t >> 5;
    int wq = wid & 3, wk = wid >> 2;  // 4q x 2k
    int lg = l >> 2;
    int iq = b * S + q0, ik = b * S + k0;
    uint32_t sb = smem_u32(sm3);
    ((float*)Rs)[t] = 0.f;

    float acc[8][2][4];
#pragma unroll
    for (int h = 0; h < 8; h++)
#pragma unroll
        for (int bn = 0; bn < 2; bn++)
#pragma unroll
            for (int r = 0; r < 4; r++) acc[h][bn][r] = 0.f;

    // loaders: Q tile has 512 rows ([h][q]) -> thread t owns rows t, t+256;
    // K tile has 256 rows ([h][k], 32 k-rows/head) -> thread t owns row t.
    int lh = t >> 6, lrow = t & 63;
    size_t qoff0 = ((size_t)lh * NI + iq + lrow) * DH;
    size_t qoff1 = ((size_t)(lh + 4) * NI + iq + lrow) * DH;
    int khh = t >> 5, krow = t & 31;
    size_t koff = ((size_t)khh * NI + ik + krow) * DH;

    // ldmatrix lane-offset derivation identical to R16 (device-verified):
    int lrow8 = l & 7, sel = l >> 3;
    uint32_t offA = (uint32_t)((wq * 16 + (sel & 1) * 8 + lrow8) * 24 + (sel >> 1) * 8);
    uint32_t offB = (uint32_t)((wk * 16 + (sel >> 1) * 8 + lrow8) * 24 + (sel & 1) * 8);

    for (int s = 0; s < 6; s++) {
        int dd0 = s * 16;
        uint32_t roQ0 = (uint32_t)t * 48, roQ1 = (uint32_t)(t + 256) * 48;
        cp16(sb + roQ0, g_Qphi + qoff0 + dd0);
        cp16(sb + roQ0 + 16, g_Qphi + qoff0 + dd0 + 8);
        cp16(sb + roQ1, g_Qphi + qoff1 + dd0);
        cp16(sb + roQ1 + 16, g_Qphi + qoff1 + dd0 + 8);
        cp16(sb + K3_QT * 2 + roQ0, g_Qplo + qoff0 + dd0);
        cp16(sb + K3_QT * 2 + roQ0 + 16, g_Qplo + qoff0 + dd0 + 8);
        cp16(sb + K3_QT * 2 + roQ1, g_Qplo + qoff1 + dd0);
        cp16(sb + K3_QT * 2 + roQ1 + 16, g_Qplo + qoff1 + dd0 + 8);
        cp16(sb + K3_QT * 4 + roQ0, g_Kphi + koff + dd0);
        cp16(sb + K3_QT * 4 + roQ0 + 16, g_Kphi + koff + dd0 + 8);
        cp16(sb + K3_QT * 4 + K3_KT * 2 + roQ0, g_Kplo + koff + dd0);
        cp16(sb + K3_QT * 4 + K3_KT * 2 + roQ0 + 16, g_Kplo + koff + dd0 + 8);
        CP_COMMIT();
        CP_WAIT0();
        __syncthreads();
#pragma unroll
        for (int h = 0; h < 8; h++) {
            uint32_t hoA = (uint32_t)(h * 64 * 24) * 2;
            uint32_t hoB = (uint32_t)(h * 32 * 24) * 2;
            uint32_t ah0, ah1, ah2, ah3, al0, al1, al2, al3;
            LDSM4(ah0, ah1, ah2, ah3, sb + hoA + offA * 2);
            LDSM4(al0, al1, al2, al3, sb + K3_QT * 2 + hoA + offA * 2);
            uint32_t bh0, bh1, bh2, bh3, bl0, bl1, bl2, bl3;
            LDSM4(bh0, bh1, bh2, bh3, sb + K3_QT * 4 + hoB + offB * 2);
            LDSM4(bl0, bl1, bl2, bl3, sb + K3_QT * 4 + K3_KT * 2 + hoB + offB * 2);
            MMA16816(acc[h][0], ah0, ah1, ah2, ah3, bh0, bh1);  // hi.hi
            MMA16816(acc[h][0], al0, al1, al2, al3, bh0, bh1);  // lo.hi
            MMA16816(acc[h][0], ah0, ah1, ah2, ah3, bl0, bl1);  // hi.lo
            MMA16816(acc[h][1], ah0, ah1, ah2, ah3, bh2, bh3);
            MMA16816(acc[h][1], al0, al1, al2, al3, bh2, bh3);
            MMA16816(acc[h][1], ah0, ah1, ah2, ah3, bl2, bl3);
        }
        __syncthreads();
    }

    // Epilogue (verified): softmax over h, aw-weighted q-reduction.
    float aw0 = g_aw[iq + wq * 16 + lg];
    float aw1 = g_aw[iq + wq * 16 + lg + 8];
#pragma unroll
    for (int bn = 0; bn < 2; bn++) {
        float rk[2][8];
#pragma unroll
        for (int ci = 0; ci < 2; ci++)
#pragma unroll
            for (int h = 0; h < 8; h++) rk[ci][h] = 0.f;
#pragma unroll
        for (int ci = 0; ci < 2; ci++)
#pragma unroll
            for (int ri = 0; ri < 2; ri++) {
                float aw = ri ? aw1 : aw0;
                float v[8];
#pragma unroll
                for (int h = 0; h < 8; h++) v[h] = acc[h][bn][ri * 2 + ci];
                float m = v[0];
#pragma unroll
                for (int h = 1; h < 8; h++) m = fmaxf(m, v[h]);
                float e[8], s = 0.f;
#pragma unroll
                for (int h = 0; h < 8; h++) { e[h] = __expf(v[h] - m); s += e[h]; }
                float w = __fdividef(aw, s);
#pragma unroll
                for (int h = 0; h < 8; h++) rk[ci][h] += w * e[h];
            }
#pragma unroll
        for (int ci = 0; ci < 2; ci++)
#pragma unroll
            for (int h = 0; h < 8; h++) {
                float r = rk[ci][h];
                r += __shfl_xor_sync(0xffffffffu, r, 4);
                r += __shfl_xor_sync(0xffffffffu, r, 8);
                r += __shfl_xor_sync(0xffffffffu, r, 16);
                if (l < 4) {
                    int kl = wk * 16 + bn * 8 + 2 * l + ci;
                    atomicAdd(&Rs[kl][h], r);
                }
            }
    }
    __syncthreads();
    atomicAdd(&g_R[(size_t)(ik + (t >> 3)) * H + (t & 7)], Rs[t >> 3][t & 7]);
}

// ---------------------------------------------------------------------------
// K4: T[b,h,m] = sum_k R[b,k,h] * X[b,k,m]
// ---------------------------------------------------------------------------
__global__ void __launch_bounds__(256) k4_T(const float* __restrict__ X) {
    __shared__ float Xs[64][64];
    __shared__ float Rsm[64][8];
    int b = blockIdx.y;
    int m0 = blockIdx.x * 64;
    int t = threadIdx.x;
    int m = t & 63, hh = t >> 6;
    float acc0 = 0.f, acc1 = 0.f;
    for (int kc = 0; kc < S; kc += 64) {
#pragma unroll
        for (int u = 0; u < 4; u++) {
            int lin = t + 256 * u;
            int r = lin >> 4, c = (lin & 15) << 2;
            *(float4*)&Xs[r][c] =
                *(const float4*)(X + (size_t)(b * S + kc + r) * DIM + m0 + c);
        }
        {
            float2 v = *(const float2*)(g_R + ((size_t)b * S + kc) * H + t * 2);
            *(float2*)&((float*)Rsm)[t * 2] = v;
        }
        __syncthreads();
#pragma unroll 8
        for (int k = 0; k < 64; k++) {
            float x = Xs[k][m];
            acc0 += Rsm[k][hh] * x;
            acc1 += Rsm[k][hh + 4] * x;
        }
        __syncthreads();
    }
    g_T[((size_t)b * H + hh) * DIM + m0 + m] = acc0;
    g_T[((size_t)b * H + hh + 4) * DIM + m0 + m] = acc1;
}

// ---------------------------------------------------------------------------
// K5: out[b,j] = sum_m Wv[j,m] * T[b, j&7, m]
// ---------------------------------------------------------------------------
__global__ void k5_out(const float* __restrict__ Wv, float* __restrict__ out) {
    int warp = threadIdx.x >> 5, lane = threadIdx.x & 31;
    int g = blockIdx.x * 8 + warp;
    int b = g / DIM, j = g % DIM;
    int h = j & 7;
    const float4* wr = (const float4*)(Wv + (size_t)j * DIM);
    const float4* tr = (const float4*)(g_T + ((size_t)b * H + h) * DIM);
    float s = 0.f;
#pragma unroll
    for (int i = 0; i < 6; i++) {
        float4 a = wr[lane + 32 * i];
        float4 c = tr[lane + 32 * i];
        s += a.x * c.x + a.y * c.y + a.z * c.z + a.w * c.w;
    }
#pragma unroll
    for (int o = 16; o; o >>= 1) s += __shfl_xor_sync(0xffffffffu, s, o);
    if (lane == 0) out[(size_t)b * DIM + j] = s;
}

// ---------------------------------------------------------------------------
extern "C" void kernel_launch(void* const* d_in, const int* in_sizes, int n_in,
                              void* d_out, int out_size) {
    const float* X    = (const float*)d_in[0];
    const int*   tags = (const int*)d_in[1];
    const float* w    = (const float*)d_in[2];
    const float* Wq   = (const float*)d_in[3];
    const float* Wk   = (const float*)d_in[4];
    const float* Wv   = (const float*)d_in[5];
    float* out = (float*)d_out;

    static int attr_set = 0;
    if (!attr_set) {
        cudaFuncSetAttribute(k3_attn, cudaFuncAttributeMaxDynamicSharedMemorySize,
                             K3_BUFB);  // 73728 B -> 2 CTAs/SM
        attr_set = 1;
    }

    k0_zeroR<<<(NI * H + 255) / 256, 256>>>();
    ksplit_sel<<<(NI * DIM / 4 + 255) / 256, 256>>>(X, 0, NI * DIM / 4);
    ksplit_sel<<<(DIM * DIM / 4 + 255) / 256, 256>>>(Wq, 1, DIM * DIM / 4);
    ksplit_sel<<<(DIM * DIM / 4 + 255) / 256, 256>>>(Wk, 2, DIM * DIM / 4);
    k1a_logits<<<NI / 8, 256>>>(X, tags, w);
    k1b_softmax<<<B, 256>>>();
    k2_mma<<<dim3(64, 12), 256, 2 * K2_BUF * sizeof(__nv_bfloat16)>>>();
    k3_attn<<<dim3(32, 16, 8), 256, K3_BUFB>>>();
    k4_T<<<dim3(12, 8), 256>>>(X);
    k5_out<<<768, 256>>>(Wv, out);
}